// round 16
// baseline (speedup 1.0000x reference)
#include <cuda_runtime.h>
#include <cuda_fp16.h>
#include <math.h>
#include <stdint.h>

// Problem constants
constexpr int L  = 4;
constexpr int D  = 64;
constexpr int H  = 8;
constexpr int HD = 512;
constexpr int G3 = 3 * HD;     // 1536
constexpr int MAXE = 100000;
constexpr int NF   = 20000;
constexpr int MAXN = 20000;

// ---------------- device scratch ----------------
__device__ __half g_GIh[(size_t)NF * G3];    // gi = feat@Wih.T + b_ih (fp16)
__device__ __half g_gh2[(size_t)NF * G3];    // gh2 = H1 @ w_hh.T + b_hh (fp16)
__device__ __half g_H1h[(size_t)NF * HD];    // h after GRU step 1 per feature
__device__ __half g_hA[(size_t)MAXE * HD];   // ping
__device__ __half g_hB[(size_t)MAXE * HD];   // pong (final hidden)
__device__ __half g_w[(size_t)G3 * HD];      // w_hh in fp16
__device__ __half g_feath[(size_t)NF * D];   // features fp16
__device__ __half g_wih[(size_t)G3 * D];     // w_ih fp16
__device__ float g_a[(size_t)MAXE * H];      // attention logits
__device__ int g_deg[MAXN];
__device__ int g_rowptr[MAXN + 1];
__device__ int g_cursor[MAXN];
__device__ int g_eidx[MAXE];

// ---------------- fast math ----------------
__device__ __forceinline__ float fsig(float x)  { return __fdividef(1.0f, 1.0f + __expf(-x)); }
__device__ __forceinline__ float ftanh(float x) { float t = __expf(2.0f * x); return 1.0f - __fdividef(2.0f, t + 1.0f); }

// ---------------- PTX helpers (plain sm_80+) ----------------
__device__ __forceinline__ uint32_t smem_u32(const void* p) {
    uint32_t a;
    asm("{ .reg .u64 t; cvta.to.shared.u64 t, %1; cvt.u32.u64 %0, t; }" : "=r"(a) : "l"(p));
    return a;
}
__device__ __forceinline__ void cpasync16(uint32_t dst, const void* src, int bytes) {
    asm volatile("cp.async.ca.shared.global [%0], [%1], 16, %2;" :: "r"(dst), "l"(src), "r"(bytes));
}
__device__ __forceinline__ void cpcommit() { asm volatile("cp.async.commit_group;" ::: "memory"); }
template<int N>
__device__ __forceinline__ void cpwait() { asm volatile("cp.async.wait_group %0;" :: "n"(N) : "memory"); }

__device__ __forceinline__ void ldsm4(uint32_t* r, uint32_t addr) {
    asm volatile("ldmatrix.sync.aligned.m8n8.x4.shared.b16 {%0,%1,%2,%3}, [%4];"
        : "=r"(r[0]), "=r"(r[1]), "=r"(r[2]), "=r"(r[3]) : "r"(addr));
}
__device__ __forceinline__ void mma16816(float* c, const uint32_t* a, uint32_t b0, uint32_t b1) {
    asm volatile("mma.sync.aligned.m16n8k16.row.col.f32.f16.f16.f32 "
        "{%0,%1,%2,%3}, {%4,%5,%6,%7}, {%8,%9}, {%0,%1,%2,%3};"
        : "+f"(c[0]), "+f"(c[1]), "+f"(c[2]), "+f"(c[3])
        : "r"(a[0]), "r"(a[1]), "r"(a[2]), "r"(a[3]), "r"(b0), "r"(b1));
}

// Swizzled tile: [R rows][64 fp16], row = 128B, ch = 16B octet
__device__ __forceinline__ uint32_t toff(int r, int ch) {
    return (uint32_t)r * 128u + (uint32_t)((ch ^ (r & 7)) * 16);
}

// SMEM layout for GEMM kernels: bias (1536B) + attn (512B) + 3-stage ring
constexpr uint32_t SM_BIAS  = 0;
constexpr uint32_t SM_ATTN  = 1536;            // 128 floats
constexpr uint32_t SM_STAGE = 2048;
constexpr uint32_t ST_A = 0;
constexpr uint32_t ST_B = 16384;
constexpr uint32_t STAGE_BYTES = 65536;
constexpr uint32_t SMEM_TOTAL = SM_STAGE + 3 * STAGE_BYTES;   // 198656

// gi3 kernel layout: b_ih (384f) + b_hh (384f) then A/B tiles
constexpr uint32_t GI3_BIH  = 0;
constexpr uint32_t GI3_BHH  = 1536;
constexpr uint32_t GI3_A    = 4096;            // 128x64 fp16 = 16KB
constexpr uint32_t GI3_B    = GI3_A + 16384;   // 384x64 fp16 = 48KB
constexpr uint32_t GI3_TOTAL = GI3_B + 49152;  // 69632

// ---------------------------------------------------------------------------
// feat -> fp16, plus g_deg zeroing folded in (runs strictly before count)
// ---------------------------------------------------------------------------
__global__ void feat2h_kernel(const float* __restrict__ feat, int n, int nn) {
    int i = blockIdx.x * blockDim.x + threadIdx.x;
    if (i < n) g_feath[i] = __float2half(feat[i]);
    if (i < nn) g_deg[i] = 0;
}

// w_hh -> fp16, w_ih -> fp16 folded in (G3*D < G3*HD)
__global__ void convert_w_kernel(const float* __restrict__ w_hh,
                                 const float* __restrict__ w_ih) {
    int i = blockIdx.x * blockDim.x + threadIdx.x;
    if (i < G3 * D) g_wih[i] = __float2half(w_ih[i]);
    if (i >= G3 * HD) return;
    g_w[i] = __float2half(w_hh[i]);
}

// ---------------------------------------------------------------------------
// GI + H1 fused: CTA = 128f x 128j x 3 gates (512 threads), K=64 single-shot.
// ---------------------------------------------------------------------------
__global__ void __launch_bounds__(512, 1)
gi3_mma_kernel(const float* __restrict__ b_ih,
               const float* __restrict__ b_hh, int nf) {
    extern __shared__ char smem[];
    uint32_t sb = smem_u32(smem);
    int tid = threadIdx.x;
    int wid = tid >> 5;
    int lane = tid & 31;
    int esub = wid & 3;
    int j0w  = (wid >> 2) * 32;
    int f0 = blockIdx.x * 128;
    int j0g = blockIdx.y * 128;

    float* s_bih = (float*)(smem + GI3_BIH);
    float* s_bhh = (float*)(smem + GI3_BHH);
    for (int i = tid; i < 384; i += 512) {
        int addr = (i >> 7) * HD + j0g + (i & 127);
        s_bih[i] = b_ih[addr];
        s_bhh[i] = b_hh[addr];
    }

#pragma unroll
    for (int it = 0; it < 2; it++) {
        int idx = tid + it * 512;
        int row = idx >> 3, ch = idx & 7;
        int f = f0 + row;
        bool ok = f < nf;
        cpasync16(sb + GI3_A + toff(row, ch),
                  g_feath + (size_t)(ok ? f : 0) * D + ch * 8, ok ? 16 : 0);
    }
#pragma unroll
    for (int it = 0; it < 6; it++) {
        int idx = tid + it * 512;
        int row = idx >> 3, ch = idx & 7;
        int g = row >> 7, jr = row & 127;
        cpasync16(sb + GI3_B + toff(row, ch),
                  g_wih + (size_t)(g * HD + j0g + jr) * D + ch * 8, 16);
    }
    cpcommit();
    cpwait<0>();
    __syncthreads();

    float acc[3][2][4][4];
#pragma unroll
    for (int g = 0; g < 3; g++)
#pragma unroll
        for (int mi = 0; mi < 2; mi++)
#pragma unroll
            for (int ni = 0; ni < 4; ni++)
#pragma unroll
                for (int c = 0; c < 4; c++) acc[g][mi][ni][c] = 0.0f;

#pragma unroll
    for (int ks = 0; ks < 4; ks++) {
        uint32_t a[2][4];
#pragma unroll
        for (int mi = 0; mi < 2; mi++) {
            int r  = esub * 32 + mi * 16 + (lane & 15);
            int ch = ks * 2 + (lane >> 4);
            ldsm4(a[mi], sb + GI3_A + toff(r, ch));
        }
#pragma unroll
        for (int g = 0; g < 3; g++) {
            uint32_t b[2][4];
#pragma unroll
            for (int p = 0; p < 2; p++) {
                int r  = g * 128 + j0w + p * 16 + ((lane >> 4) << 3) + (lane & 7);
                int ch = ks * 2 + ((lane >> 3) & 1);
                ldsm4(b[p], sb + GI3_B + toff(r, ch));
            }
#pragma unroll
            for (int mi = 0; mi < 2; mi++)
#pragma unroll
                for (int p = 0; p < 2; p++)
#pragma unroll
                    for (int q = 0; q < 2; q++)
                        mma16816(acc[g][mi][p * 2 + q], a[mi], b[p][q * 2], b[p][q * 2 + 1]);
        }
    }

#pragma unroll
    for (int mi = 0; mi < 2; mi++) {
#pragma unroll
        for (int rh = 0; rh < 2; rh++) {
            int f = f0 + esub * 32 + mi * 16 + rh * 8 + (lane >> 2);
            if (f >= nf) continue;
#pragma unroll
            for (int ni = 0; ni < 4; ni++) {
                int jl = j0w + ni * 8 + (lane & 3) * 2;
                int j  = j0g + jl;
                float gr0 = acc[0][mi][ni][rh * 2]     + s_bih[jl];
                float gr1 = acc[0][mi][ni][rh * 2 + 1] + s_bih[jl + 1];
                float gz0 = acc[1][mi][ni][rh * 2]     + s_bih[128 + jl];
                float gz1 = acc[1][mi][ni][rh * 2 + 1] + s_bih[128 + jl + 1];
                float gn0 = acc[2][mi][ni][rh * 2]     + s_bih[256 + jl];
                float gn1 = acc[2][mi][ni][rh * 2 + 1] + s_bih[256 + jl + 1];
                __half2 o;
                o.x = __float2half(gr0); o.y = __float2half(gr1);
                *(__half2*)(g_GIh + (size_t)f * G3 + j) = o;
                o.x = __float2half(gz0); o.y = __float2half(gz1);
                *(__half2*)(g_GIh + (size_t)f * G3 + HD + j) = o;
                o.x = __float2half(gn0); o.y = __float2half(gn1);
                *(__half2*)(g_GIh + (size_t)f * G3 + 2 * HD + j) = o;
                float r0 = fsig(gr0 + s_bhh[jl]);
                float r1 = fsig(gr1 + s_bhh[jl + 1]);
                float z0 = fsig(gz0 + s_bhh[128 + jl]);
                float z1 = fsig(gz1 + s_bhh[128 + jl + 1]);
                float n0 = ftanh(gn0 + r0 * s_bhh[256 + jl]);
                float n1 = ftanh(gn1 + r1 * s_bhh[256 + jl + 1]);
                __half2 h;
                h.x = __float2half((1.0f - z0) * n0);
                h.y = __float2half((1.0f - z1) * n1);
                *(__half2*)(g_H1h + (size_t)f * HD + j) = h;
            }
        }
    }
}

// ---------------------------------------------------------------------------
// GH2 = H1h @ w_hh.T + b_hh  [nf, 1536]
// ---------------------------------------------------------------------------
__global__ void __launch_bounds__(512, 1)
gh2_mma_kernel(const float* __restrict__ b_hh, int nf) {
    extern __shared__ char smem[];
    uint32_t sb = smem_u32(smem);
    int tid = threadIdx.x;
    int wid = tid >> 5;
    int lane = tid & 31;
    int esub = wid & 3;
    int j0w  = (wid >> 2) * 32;
    int e0 = blockIdx.x * 128;
    int j0g = blockIdx.y * 128;

    float* s_bias = (float*)(smem + SM_BIAS);
    for (int i = tid; i < 384; i += 512)
        s_bias[i] = b_hh[(i >> 7) * HD + j0g + (i & 127)];

    auto load_chunk = [&](int kc, int s) {
        uint32_t base = sb + SM_STAGE + (uint32_t)s * STAGE_BYTES;
        int k0 = kc * 64;
#pragma unroll
        for (int it = 0; it < 2; it++) {
            int idx = tid + it * 512;
            int row = idx >> 3, ch = idx & 7;
            int f = e0 + row;
            bool ok = f < nf;
            cpasync16(base + ST_A + toff(row, ch),
                      g_H1h + (size_t)(ok ? f : 0) * HD + k0 + ch * 8, ok ? 16 : 0);
        }
#pragma unroll
        for (int it = 0; it < 6; it++) {
            int idx = tid + it * 512;
            int row = idx >> 3, ch = idx & 7;
            int g = row >> 7, jr = row & 127;
            cpasync16(base + ST_B + toff(row, ch),
                      g_w + (size_t)(g * HD + j0g + jr) * HD + k0 + ch * 8, 16);
        }
        cpcommit();
    };

    float acc[3][2][4][4];
#pragma unroll
    for (int g = 0; g < 3; g++)
#pragma unroll
        for (int mi = 0; mi < 2; mi++)
#pragma unroll
            for (int ni = 0; ni < 4; ni++)
#pragma unroll
                for (int c = 0; c < 4; c++) acc[g][mi][ni][c] = 0.0f;

    load_chunk(0, 0);
    load_chunk(1, 1);
    cpwait<1>();
    __syncthreads();

    for (int kc = 0; kc < 8; kc++) {
        if (kc + 2 < 8) load_chunk(kc + 2, (kc + 2) % 3);

        uint32_t base = sb + SM_STAGE + (uint32_t)(kc % 3) * STAGE_BYTES;
#pragma unroll
        for (int ks = 0; ks < 4; ks++) {
            uint32_t a[2][4];
#pragma unroll
            for (int mi = 0; mi < 2; mi++) {
                int r  = esub * 32 + mi * 16 + (lane & 15);
                int ch = ks * 2 + (lane >> 4);
                ldsm4(a[mi], base + ST_A + toff(r, ch));
            }
#pragma unroll
            for (int g = 0; g < 3; g++) {
                uint32_t b[2][4];
#pragma unroll
                for (int p = 0; p < 2; p++) {
                    int r  = g * 128 + j0w + p * 16 + ((lane >> 4) << 3) + (lane & 7);
                    int ch = ks * 2 + ((lane >> 3) & 1);
                    ldsm4(b[p], base + ST_B + toff(r, ch));
                }
#pragma unroll
                for (int mi = 0; mi < 2; mi++)
#pragma unroll
                    for (int p = 0; p < 2; p++)
#pragma unroll
                        for (int q = 0; q < 2; q++)
                            mma16816(acc[g][mi][p * 2 + q], a[mi], b[p][q * 2], b[p][q * 2 + 1]);
            }
        }
        if (kc < 7) {
            if (kc + 2 < 8) cpwait<1>(); else cpwait<0>();
            __syncthreads();
        }
    }

#pragma unroll
    for (int mi = 0; mi < 2; mi++) {
#pragma unroll
        for (int rh = 0; rh < 2; rh++) {
            int f = e0 + esub * 32 + mi * 16 + rh * 8 + (lane >> 2);
            if (f >= nf) continue;
#pragma unroll
            for (int ni = 0; ni < 4; ni++) {
                int jl = j0w + ni * 8 + (lane & 3) * 2;
                int j  = j0g + jl;
#pragma unroll
                for (int g = 0; g < 3; g++) {
                    float v0 = acc[g][mi][ni][rh * 2]     + s_bias[g * 128 + jl];
                    float v1 = acc[g][mi][ni][rh * 2 + 1] + s_bias[g * 128 + jl + 1];
                    __half2 o;
                    o.x = __float2half(v0);
                    o.y = __float2half(v1);
                    *(__half2*)(g_gh2 + (size_t)f * G3 + g * HD + j) = o;
                }
            }
        }
    }
}

// ---------------------------------------------------------------------------
// Step-1 per-edge elementwise: h2[e] = GRUcell(GH2[f0] + GI[f1], H1[f0]) -> hB
// ---------------------------------------------------------------------------
__global__ void __launch_bounds__(256)
step1_edge_kernel(const int* __restrict__ mpi, int Ee) {
    int warp = (blockIdx.x * blockDim.x + threadIdx.x) >> 5;
    int lane = threadIdx.x & 31;
    if (warp >= Ee) return;
    int f0 = mpi[(size_t)warp * L];
    int f1 = mpi[(size_t)warp * L + 1];
    int j = lane * 16;

    const uint4* h1p = (const uint4*)(g_H1h + (size_t)f0 * HD + j);
    const uint4* ghr = (const uint4*)(g_gh2 + (size_t)f0 * G3 + j);
    const uint4* ghz = (const uint4*)(g_gh2 + (size_t)f0 * G3 + HD + j);
    const uint4* ghn = (const uint4*)(g_gh2 + (size_t)f0 * G3 + 2 * HD + j);
    const uint4* gir = (const uint4*)(g_GIh + (size_t)f1 * G3 + j);
    const uint4* giz = (const uint4*)(g_GIh + (size_t)f1 * G3 + HD + j);
    const uint4* gin = (const uint4*)(g_GIh + (size_t)f1 * G3 + 2 * HD + j);
    uint4* outp = (uint4*)(g_hB + (size_t)warp * HD + j);

#pragma unroll
    for (int half16 = 0; half16 < 2; half16++) {
        uint4 qh1 = h1p[half16];
        uint4 qgr = ghr[half16], qgz = ghz[half16], qgn = ghn[half16];
        uint4 qir = gir[half16], qiz = giz[half16], qin = gin[half16];
        const __half2* h1v = (const __half2*)&qh1;
        const __half2* grv = (const __half2*)&qgr;
        const __half2* gzv = (const __half2*)&qgz;
        const __half2* gnv = (const __half2*)&qgn;
        const __half2* irv = (const __half2*)&qir;
        const __half2* izv = (const __half2*)&qiz;
        const __half2* inv = (const __half2*)&qin;
        uint4 qo;
        __half2* ov = (__half2*)&qo;
#pragma unroll
        for (int k = 0; k < 4; k++) {
            float r0 = fsig(__half2float(grv[k].x) + __half2float(irv[k].x));
            float r1 = fsig(__half2float(grv[k].y) + __half2float(irv[k].y));
            float z0 = fsig(__half2float(gzv[k].x) + __half2float(izv[k].x));
            float z1 = fsig(__half2float(gzv[k].y) + __half2float(izv[k].y));
            float n0 = ftanh(__half2float(inv[k].x) + r0 * __half2float(gnv[k].x));
            float n1 = ftanh(__half2float(inv[k].y) + r1 * __half2float(gnv[k].y));
            float h0 = (1.0f - z0) * n0 + z0 * __half2float(h1v[k].x);
            float h1 = (1.0f - z1) * n1 + z1 * __half2float(h1v[k].y);
            ov[k].x = __float2half(h0);
            ov[k].y = __float2half(h1);
        }
        outp[half16] = qo;
    }
}

// ---------------------------------------------------------------------------
// GRU step, templated on MODE (R11-exact hot kernel).
// MODE 1: A = hB, O = hA  (t = 2)
// MODE 2: A = hA, O = hB  (t = 3) + fused attention logits
// ---------------------------------------------------------------------------
template<int MODE>
__global__ void __launch_bounds__(512, 1)
gru_mma_kernel(const int* __restrict__ mpi,
               const float* __restrict__ b_hh,
               const float* __restrict__ attn,
               int Ee, int t) {
    extern __shared__ char smem[];
    uint32_t sb = smem_u32(smem);
    int tid = threadIdx.x;
    int wid = tid >> 5;
    int lane = tid & 31;
    int esub = wid & 3;
    int j0w  = (wid >> 2) * 32;

    const __half* __restrict__ A = (MODE == 1) ? g_hB : g_hA;
    __half* __restrict__       O = (MODE == 1) ? g_hA : g_hB;

    int e0 = blockIdx.x * 128;
    int j0g = blockIdx.y * 128;

    float* s_bias = (float*)(smem + SM_BIAS);
    for (int i = tid; i < 384; i += 512)
        s_bias[i] = b_hh[(i >> 7) * HD + j0g + (i & 127)];
    float* s_attn = (float*)(smem + SM_ATTN);
    if (MODE == 2) {
        if (tid < 128) s_attn[tid] = attn[j0g + tid];
    }

    auto load_chunk = [&](int kc, int s) {
        uint32_t base = sb + SM_STAGE + (uint32_t)s * STAGE_BYTES;
        int k0 = kc * 64;
#pragma unroll
        for (int it = 0; it < 2; it++) {
            int idx = tid + it * 512;
            int row = idx >> 3, ch = idx & 7;
            int e = e0 + row;
            bool ok = e < Ee;
            cpasync16(base + ST_A + toff(row, ch),
                      A + (size_t)(ok ? e : 0) * HD + k0 + ch * 8, ok ? 16 : 0);
        }
#pragma unroll
        for (int it = 0; it < 6; it++) {
            int idx = tid + it * 512;
            int row = idx >> 3, ch = idx & 7;
            int g = row >> 7, jr = row & 127;
            cpasync16(base + ST_B + toff(row, ch),
                      g_w + (size_t)(g * HD + j0g + jr) * HD + k0 + ch * 8, 16);
        }
        cpcommit();
    };

    float acc[3][2][4][4];
#pragma unroll
    for (int g = 0; g < 3; g++)
#pragma unroll
        for (int mi = 0; mi < 2; mi++)
#pragma unroll
            for (int ni = 0; ni < 4; ni++)
#pragma unroll
                for (int c = 0; c < 4; c++) acc[g][mi][ni][c] = 0.0f;

    load_chunk(0, 0);
    load_chunk(1, 1);
    cpwait<1>();
    __syncthreads();

    for (int kc = 0; kc < 8; kc++) {
        if (kc + 2 < 8) load_chunk(kc + 2, (kc + 2) % 3);

        uint32_t base = sb + SM_STAGE + (uint32_t)(kc % 3) * STAGE_BYTES;
#pragma unroll
        for (int ks = 0; ks < 4; ks++) {
            uint32_t a[2][4];
#pragma unroll
            for (int mi = 0; mi < 2; mi++) {
                int r  = esub * 32 + mi * 16 + (lane & 15);
                int ch = ks * 2 + (lane >> 4);
                ldsm4(a[mi], base + ST_A + toff(r, ch));
            }
#pragma unroll
            for (int g = 0; g < 3; g++) {
                uint32_t b[2][4];
#pragma unroll
                for (int p = 0; p < 2; p++) {
                    int r  = g * 128 + j0w + p * 16 + ((lane >> 4) << 3) + (lane & 7);
                    int ch = ks * 2 + ((lane >> 3) & 1);
                    ldsm4(b[p], base + ST_B + toff(r, ch));
                }
#pragma unroll
                for (int mi = 0; mi < 2; mi++)
#pragma unroll
                    for (int p = 0; p < 2; p++)
#pragma unroll
                        for (int q = 0; q < 2; q++)
                            mma16816(acc[g][mi][p * 2 + q], a[mi], b[p][q * 2], b[p][q * 2 + 1]);
            }
        }
        if (kc < 7) {
            if (kc + 2 < 8) cpwait<1>(); else cpwait<0>();
            __syncthreads();
        }
    }

    // scratch for fused logits (stage ring dead after mainloop)
    float* s_logit = (float*)(smem + SM_STAGE);
    int hl = (wid >> 2) >> 1;
    if (MODE == 2) {
        __syncthreads();
        for (int i = tid; i < 256; i += 512) s_logit[i] = 0.0f;
        __syncthreads();
    }

#pragma unroll
    for (int mi = 0; mi < 2; mi++) {
#pragma unroll
        for (int rh = 0; rh < 2; rh++) {
            int rl = esub * 32 + mi * 16 + rh * 8 + (lane >> 2);
            int e = e0 + rl;
            float p = 0.0f;
            if (e < Ee) {
                int f = mpi[(size_t)e * L + t];
                const __half* giRow = g_GIh + (size_t)f * G3;
#pragma unroll
                for (int ni = 0; ni < 4; ni++) {
                    int jl = j0w + ni * 8 + (lane & 3) * 2;
                    int j  = j0g + jl;
                    float gr0 = acc[0][mi][ni][rh * 2], gr1 = acc[0][mi][ni][rh * 2 + 1];
                    float gz0 = acc[1][mi][ni][rh * 2], gz1 = acc[1][mi][ni][rh * 2 + 1];
                    float gn0 = acc[2][mi][ni][rh * 2], gn1 = acc[2][mi][ni][rh * 2 + 1];
                    __half2 ir = *(const __half2*)(giRow + j);
                    __half2 iz = *(const __half2*)(giRow + HD + j);
                    __half2 in = *(const __half2*)(giRow + 2 * HD + j);
                    float r0 = fsig(gr0 + s_bias[jl]           + __half2float(ir.x));
                    float r1 = fsig(gr1 + s_bias[jl + 1]       + __half2float(ir.y));
                    float z0 = fsig(gz0 + s_bias[128 + jl]     + __half2float(iz.x));
                    float z1 = fsig(gz1 + s_bias[128 + jl + 1] + __half2float(iz.y));
                    float n0 = ftanh(__half2float(in.x) + r0 * (gn0 + s_bias[256 + jl]));
                    float n1 = ftanh(__half2float(in.y) + r1 * (gn1 + s_bias[256 + jl + 1]));
                    __half2 hp = *(const __half2*)(A + (size_t)e * HD + j);
                    float h0 = (1.0f - z0) * n0 + z0 * __half2float(hp.x);
                    float h1 = (1.0f - z1) * n1 + z1 * __half2float(hp.y);
                    __half2 oh;
                    oh.x = __float2half(h0);
                    oh.y = __float2half(h1);
                    *(__half2*)(O + (size_t)e * HD + j) = oh;
                    if (MODE == 2) {
                        p += h0 * s_attn[jl] + h1 * s_attn[jl + 1];
                    }
                }
            }
            if (MODE == 2) {
                p += __shfl_xor_sync(0xffffffff, p, 1);
                p += __shfl_xor_sync(0xffffffff, p, 2);
                if ((lane & 3) == 0 && e < Ee)
                    atomicAdd(&s_logit[rl * 2 + hl], p);
            }
        }
    }

    if (MODE == 2) {
        __syncthreads();
        if (tid < 256) {
            int rl = tid >> 1, h2 = tid & 1;
            int e = e0 + rl;
            if (e < Ee) {
                float v = s_logit[tid];
                g_a[(size_t)e * H + (j0g >> 6) + h2] = v > 0.0f ? v : 0.001f * v;
            }
        }
    }
}

// ---------------------------------------------------------------------------
// CSR build
// ---------------------------------------------------------------------------
__global__ void count_kernel(const int* __restrict__ dst, int Ee) {
    int i = blockIdx.x * blockDim.x + threadIdx.x;
    if (i < Ee) atomicAdd(&g_deg[dst[i]], 1);
}
__global__ void scan_kernel(int nn, int Ee) {
    __shared__ int ssum[1024];
    int t = threadIdx.x;
    int chunk = (nn + 1023) >> 10;
    int lo = t * chunk, hi = lo + chunk;
    if (hi > nn) hi = nn;
    int s = 0;
    for (int i = lo; i < hi; i++) s += g_deg[i];
    ssum[t] = s;
    __syncthreads();
    for (int off = 1; off < 1024; off <<= 1) {
        int v = (t >= off) ? ssum[t - off] : 0;
        __syncthreads();
        ssum[t] += v;
        __syncthreads();
    }
    int run = (t == 0) ? 0 : ssum[t - 1];
    for (int i = lo; i < hi; i++) {
        g_rowptr[i] = run;
        g_cursor[i] = run;
        run += g_deg[i];
    }
    if (t == 0) g_rowptr[nn] = Ee;
}
__global__ void fill_kernel(const int* __restrict__ dst, int Ee) {
    int i = blockIdx.x * blockDim.x + threadIdx.x;
    if (i < Ee) {
        int p = atomicAdd(&g_cursor[dst[i]], 1);
        g_eidx[p] = i;
    }
}

// ---------------------------------------------------------------------------
// Per-node segment softmax + weighted scatter: one warp per node, no atomics.
// ---------------------------------------------------------------------------
__global__ void node_attn_kernel(float* __restrict__ out, int nn) {
    int warp = (blockIdx.x * blockDim.x + threadIdx.x) >> 5;
    int lane = threadIdx.x & 31;
    if (warp >= nn) return;
    int start = g_rowptr[warp];
    int end   = g_rowptr[warp + 1];

    int sub = lane >> 3;
    int hh  = lane & 7;
    float m = -3.0e38f;
    for (int i = start + sub; i < end; i += 4)
        m = fmaxf(m, g_a[(size_t)g_eidx[i] * H + hh]);
    m = fmaxf(m, __shfl_xor_sync(0xffffffff, m, 8));
    m = fmaxf(m, __shfl_xor_sync(0xffffffff, m, 16));
    float s = 0.0f;
    for (int i = start + sub; i < end; i += 4)
        s += __expf(g_a[(size_t)g_eidx[i] * H + hh] - m);
    s += __shfl_xor_sync(0xffffffff, s, 8);
    s += __shfl_xor_sync(0xffffffff, s, 16);

    int h = lane >> 2;
    float mh  = __shfl_sync(0xffffffff, m, h);
    float inv = __fdividef(1.0f, fmaxf(__shfl_sync(0xffffffff, s, h), 1e-12f));

    float acc[16];
#pragma unroll
    for (int k = 0; k < 16; k++) acc[k] = 0.0f;

    for (int i = start; i < end; i++) {
        int e = g_eidx[i];
        float w = __expf(g_a[(size_t)e * H + h] - mh) * inv;
        const uint4* p = (const uint4*)(g_hB + (size_t)e * HD + lane * 16);
        uint4 q0 = p[0], q1 = p[1];
        const __half2* c0 = (const __half2*)&q0;
        const __half2* c1 = (const __half2*)&q1;
#pragma unroll
        for (int k = 0; k < 4; k++) {
            acc[2 * k]     += w * __half2float(c0[k].x);
            acc[2 * k + 1] += w * __half2float(c0[k].y);
            acc[8 + 2 * k]     += w * __half2float(c1[k].x);
            acc[8 + 2 * k + 1] += w * __half2float(c1[k].y);
        }
    }
    float4* o = (float4*)(out + (size_t)warp * HD + lane * 16);
#pragma unroll
    for (int k = 0; k < 4; k++)
        o[k] = make_float4(acc[4 * k], acc[4 * k + 1], acc[4 * k + 2], acc[4 * k + 3]);
}

// ---------------------------------------------------------------------------
extern "C" void kernel_launch(void* const* d_in, const int* in_sizes, int n_in,
                              void* d_out, int out_size) {
    int off = (n_in >= 9) ? 1 : 0;
    const float* feat = (const float*)d_in[0];
    const int*   mpi  = (const int*)d_in[1];
    const int*   dst  = (const int*)d_in[2];
    const float* w_ih = (const float*)d_in[3 + off];
    const float* w_hh = (const float*)d_in[4 + off];
    const float* b_ih = (const float*)d_in[5 + off];
    const float* b_hh = (const float*)d_in[6 + off];
    const float* attn = (const float*)d_in[7 + off];
    float* out = (float*)d_out;

    int E  = in_sizes[2];
    int nf = in_sizes[0] / D;
    int nn = out_size / HD;

    cudaFuncSetAttribute(gru_mma_kernel<1>, cudaFuncAttributeMaxDynamicSharedMemorySize, SMEM_TOTAL);
    cudaFuncSetAttribute(gru_mma_kernel<2>, cudaFuncAttributeMaxDynamicSharedMemorySize, SMEM_TOTAL);
    cudaFuncSetAttribute(gh2_mma_kernel, cudaFuncAttributeMaxDynamicSharedMemorySize, SMEM_TOTAL);
    cudaFuncSetAttribute(gi3_mma_kernel, cudaFuncAttributeMaxDynamicSharedMemorySize, GI3_TOTAL);

    feat2h_kernel<<<(nf * D + 255) / 256, 256>>>(feat, nf * D, nn);     // + g_deg zero
    convert_w_kernel<<<(G3 * HD + 255) / 256, 256>>>(w_hh, w_ih);       // + w_ih convert

    // GI + fused H1
    dim3 gi3_grid((nf + 127) / 128, HD / 128);
    gi3_mma_kernel<<<gi3_grid, 512, GI3_TOTAL>>>(b_ih, b_hh, nf);

    // CSR build
    count_kernel<<<(E + 255) / 256, 256>>>(dst, E);
    scan_kernel<<<1, 1024>>>(nn, E);
    fill_kernel<<<(E + 255) / 256, 256>>>(dst, E);

    // Step 1 dedup: per-feature GEMM + per-edge elementwise cell
    dim3 gh2_grid((nf + 127) / 128, HD / 128);
    gh2_mma_kernel<<<gh2_grid, 512, SMEM_TOTAL>>>(b_hh, nf);
    step1_edge_kernel<<<(E * 32 + 255) / 256, 256>>>(mpi, E);   // -> hB

    // Steps 2,3 (step 3 fuses attention logits into its epilogue)
    dim3 gru_grid((E + 127) / 128, HD / 128);
    gru_mma_kernel<1><<<gru_grid, 512, SMEM_TOTAL>>>(mpi, b_hh, attn, E, 2);  // hB -> hA
    gru_mma_kernel<2><<<gru_grid, 512, SMEM_TOTAL>>>(mpi, b_hh, attn, E, 3);  // hA -> hB (+logits)

    node_attn_kernel<<<(nn * 32 + 255) / 256, 256>>>(out, nn);
}

// round 17
// speedup vs baseline: 1.0060x; 1.0060x over previous
#include <cuda_runtime.h>
#include <cuda_fp16.h>
#include <math.h>
#include <stdint.h>

// Problem constants
constexpr int L  = 4;
constexpr int D  = 64;
constexpr int H  = 8;
constexpr int HD = 512;
constexpr int G3 = 3 * HD;     // 1536
constexpr int MAXE = 100000;
constexpr int NF   = 20000;
constexpr int MAXN = 20000;

// ---------------- device scratch ----------------
__device__ __half g_GIh[(size_t)NF * G3];    // gi = feat@Wih.T + b_ih (fp16)
__device__ __half g_gh2[(size_t)NF * G3];    // gh2 = H1 @ w_hh.T + b_hh (fp16)
__device__ __half g_H1h[(size_t)NF * HD];    // h after GRU step 1 per feature
__device__ __half g_hA[(size_t)MAXE * HD];   // ping
__device__ __half g_hB[(size_t)MAXE * HD];   // pong (final hidden)
__device__ __half g_w[(size_t)G3 * HD];      // w_hh in fp16
__device__ __half g_feath[(size_t)NF * D];   // features fp16
__device__ __half g_wih[(size_t)G3 * D];     // w_ih fp16
__device__ float g_a[(size_t)MAXE * H];      // attention logits
__device__ int g_deg[MAXN];
__device__ int g_rowptr[MAXN + 1];
__device__ int g_cursor[MAXN];
__device__ int g_eidx[MAXE];

// ---------------- fast math ----------------
__device__ __forceinline__ float fsig(float x)  { return __fdividef(1.0f, 1.0f + __expf(-x)); }
__device__ __forceinline__ float ftanh(float x) { float t = __expf(2.0f * x); return 1.0f - __fdividef(2.0f, t + 1.0f); }

// ---------------- PTX helpers (plain sm_80+) ----------------
__device__ __forceinline__ uint32_t smem_u32(const void* p) {
    uint32_t a;
    asm("{ .reg .u64 t; cvta.to.shared.u64 t, %1; cvt.u32.u64 %0, t; }" : "=r"(a) : "l"(p));
    return a;
}
__device__ __forceinline__ void cpasync16(uint32_t dst, const void* src, int bytes) {
    asm volatile("cp.async.ca.shared.global [%0], [%1], 16, %2;" :: "r"(dst), "l"(src), "r"(bytes));
}
__device__ __forceinline__ void cpcommit() { asm volatile("cp.async.commit_group;" ::: "memory"); }
template<int N>
__device__ __forceinline__ void cpwait() { asm volatile("cp.async.wait_group %0;" :: "n"(N) : "memory"); }

__device__ __forceinline__ void ldsm4(uint32_t* r, uint32_t addr) {
    asm volatile("ldmatrix.sync.aligned.m8n8.x4.shared.b16 {%0,%1,%2,%3}, [%4];"
        : "=r"(r[0]), "=r"(r[1]), "=r"(r[2]), "=r"(r[3]) : "r"(addr));
}
__device__ __forceinline__ void mma16816(float* c, const uint32_t* a, uint32_t b0, uint32_t b1) {
    asm volatile("mma.sync.aligned.m16n8k16.row.col.f32.f16.f16.f32 "
        "{%0,%1,%2,%3}, {%4,%5,%6,%7}, {%8,%9}, {%0,%1,%2,%3};"
        : "+f"(c[0]), "+f"(c[1]), "+f"(c[2]), "+f"(c[3])
        : "r"(a[0]), "r"(a[1]), "r"(a[2]), "r"(a[3]), "r"(b0), "r"(b1));
}

// Swizzled tile: [R rows][64 fp16], row = 128B, ch = 16B octet
__device__ __forceinline__ uint32_t toff(int r, int ch) {
    return (uint32_t)r * 128u + (uint32_t)((ch ^ (r & 7)) * 16);
}

// SMEM layout for GEMM kernels: bias (1536B) + attn (512B) + 3-stage ring
constexpr uint32_t SM_BIAS  = 0;
constexpr uint32_t SM_ATTN  = 1536;            // 128 floats
constexpr uint32_t SM_STAGE = 2048;
constexpr uint32_t ST_A = 0;
constexpr uint32_t ST_B = 16384;
constexpr uint32_t STAGE_BYTES = 65536;
constexpr uint32_t SMEM_TOTAL = SM_STAGE + 3 * STAGE_BYTES;   // 198656

// gi3 kernel layout: b_ih (384f) + b_hh (384f) then A/B tiles
constexpr uint32_t GI3_BIH  = 0;
constexpr uint32_t GI3_BHH  = 1536;
constexpr uint32_t GI3_A    = 4096;            // 128x64 fp16 = 16KB
constexpr uint32_t GI3_B    = GI3_A + 16384;   // 384x64 fp16 = 48KB
constexpr uint32_t GI3_TOTAL = GI3_B + 49152;  // 69632

// ---------------------------------------------------------------------------
__global__ void init_kernel(int nn) {
    int i = blockIdx.x * blockDim.x + threadIdx.x;
    if (i < nn) g_deg[i] = 0;
}

// ---------------------------------------------------------------------------
__global__ void feat2h_kernel(const float* __restrict__ feat, int n) {
    int i = blockIdx.x * blockDim.x + threadIdx.x;
    if (i < n) g_feath[i] = __float2half(feat[i]);
}
__global__ void convert_w_kernel(const float* __restrict__ w_hh) {
    int i = blockIdx.x * blockDim.x + threadIdx.x;
    if (i >= G3 * HD) return;
    g_w[i] = __float2half(w_hh[i]);
}
__global__ void convert_wih_kernel(const float* __restrict__ w_ih) {
    int i = blockIdx.x * blockDim.x + threadIdx.x;
    if (i >= G3 * D) return;
    g_wih[i] = __float2half(w_ih[i]);
}

// ---------------------------------------------------------------------------
// GI + H1 fused: CTA = 128f x 128j x 3 gates (512 threads), K=64 single-shot.
// ---------------------------------------------------------------------------
__global__ void __launch_bounds__(512, 1)
gi3_mma_kernel(const float* __restrict__ b_ih,
               const float* __restrict__ b_hh, int nf) {
    extern __shared__ char smem[];
    uint32_t sb = smem_u32(smem);
    int tid = threadIdx.x;
    int wid = tid >> 5;
    int lane = tid & 31;
    int esub = wid & 3;
    int j0w  = (wid >> 2) * 32;
    int f0 = blockIdx.x * 128;
    int j0g = blockIdx.y * 128;

    float* s_bih = (float*)(smem + GI3_BIH);
    float* s_bhh = (float*)(smem + GI3_BHH);
    for (int i = tid; i < 384; i += 512) {
        int addr = (i >> 7) * HD + j0g + (i & 127);
        s_bih[i] = b_ih[addr];
        s_bhh[i] = b_hh[addr];
    }

#pragma unroll
    for (int it = 0; it < 2; it++) {
        int idx = tid + it * 512;
        int row = idx >> 3, ch = idx & 7;
        int f = f0 + row;
        bool ok = f < nf;
        cpasync16(sb + GI3_A + toff(row, ch),
                  g_feath + (size_t)(ok ? f : 0) * D + ch * 8, ok ? 16 : 0);
    }
#pragma unroll
    for (int it = 0; it < 6; it++) {
        int idx = tid + it * 512;
        int row = idx >> 3, ch = idx & 7;
        int g = row >> 7, jr = row & 127;
        cpasync16(sb + GI3_B + toff(row, ch),
                  g_wih + (size_t)(g * HD + j0g + jr) * D + ch * 8, 16);
    }
    cpcommit();
    cpwait<0>();
    __syncthreads();

    float acc[3][2][4][4];
#pragma unroll
    for (int g = 0; g < 3; g++)
#pragma unroll
        for (int mi = 0; mi < 2; mi++)
#pragma unroll
            for (int ni = 0; ni < 4; ni++)
#pragma unroll
                for (int c = 0; c < 4; c++) acc[g][mi][ni][c] = 0.0f;

#pragma unroll
    for (int ks = 0; ks < 4; ks++) {
        uint32_t a[2][4];
#pragma unroll
        for (int mi = 0; mi < 2; mi++) {
            int r  = esub * 32 + mi * 16 + (lane & 15);
            int ch = ks * 2 + (lane >> 4);
            ldsm4(a[mi], sb + GI3_A + toff(r, ch));
        }
#pragma unroll
        for (int g = 0; g < 3; g++) {
            uint32_t b[2][4];
#pragma unroll
            for (int p = 0; p < 2; p++) {
                int r  = g * 128 + j0w + p * 16 + ((lane >> 4) << 3) + (lane & 7);
                int ch = ks * 2 + ((lane >> 3) & 1);
                ldsm4(b[p], sb + GI3_B + toff(r, ch));
            }
#pragma unroll
            for (int mi = 0; mi < 2; mi++)
#pragma unroll
                for (int p = 0; p < 2; p++)
#pragma unroll
                    for (int q = 0; q < 2; q++)
                        mma16816(acc[g][mi][p * 2 + q], a[mi], b[p][q * 2], b[p][q * 2 + 1]);
        }
    }

#pragma unroll
    for (int mi = 0; mi < 2; mi++) {
#pragma unroll
        for (int rh = 0; rh < 2; rh++) {
            int f = f0 + esub * 32 + mi * 16 + rh * 8 + (lane >> 2);
            if (f >= nf) continue;
#pragma unroll
            for (int ni = 0; ni < 4; ni++) {
                int jl = j0w + ni * 8 + (lane & 3) * 2;
                int j  = j0g + jl;
                float gr0 = acc[0][mi][ni][rh * 2]     + s_bih[jl];
                float gr1 = acc[0][mi][ni][rh * 2 + 1] + s_bih[jl + 1];
                float gz0 = acc[1][mi][ni][rh * 2]     + s_bih[128 + jl];
                float gz1 = acc[1][mi][ni][rh * 2 + 1] + s_bih[128 + jl + 1];
                float gn0 = acc[2][mi][ni][rh * 2]     + s_bih[256 + jl];
                float gn1 = acc[2][mi][ni][rh * 2 + 1] + s_bih[256 + jl + 1];
                __half2 o;
                o.x = __float2half(gr0); o.y = __float2half(gr1);
                *(__half2*)(g_GIh + (size_t)f * G3 + j) = o;
                o.x = __float2half(gz0); o.y = __float2half(gz1);
                *(__half2*)(g_GIh + (size_t)f * G3 + HD + j) = o;
                o.x = __float2half(gn0); o.y = __float2half(gn1);
                *(__half2*)(g_GIh + (size_t)f * G3 + 2 * HD + j) = o;
                float r0 = fsig(gr0 + s_bhh[jl]);
                float r1 = fsig(gr1 + s_bhh[jl + 1]);
                float z0 = fsig(gz0 + s_bhh[128 + jl]);
                float z1 = fsig(gz1 + s_bhh[128 + jl + 1]);
                float n0 = ftanh(gn0 + r0 * s_bhh[256 + jl]);
                float n1 = ftanh(gn1 + r1 * s_bhh[256 + jl + 1]);
                __half2 h;
                h.x = __float2half((1.0f - z0) * n0);
                h.y = __float2half((1.0f - z1) * n1);
                *(__half2*)(g_H1h + (size_t)f * HD + j) = h;
            }
        }
    }
}

// ---------------------------------------------------------------------------
// GH2 = H1h @ w_hh.T + b_hh  [nf, 1536]
// ---------------------------------------------------------------------------
__global__ void __launch_bounds__(512, 1)
gh2_mma_kernel(const float* __restrict__ b_hh, int nf) {
    extern __shared__ char smem[];
    uint32_t sb = smem_u32(smem);
    int tid = threadIdx.x;
    int wid = tid >> 5;
    int lane = tid & 31;
    int esub = wid & 3;
    int j0w  = (wid >> 2) * 32;
    int e0 = blockIdx.x * 128;
    int j0g = blockIdx.y * 128;

    float* s_bias = (float*)(smem + SM_BIAS);
    for (int i = tid; i < 384; i += 512)
        s_bias[i] = b_hh[(i >> 7) * HD + j0g + (i & 127)];

    auto load_chunk = [&](int kc, int s) {
        uint32_t base = sb + SM_STAGE + (uint32_t)s * STAGE_BYTES;
        int k0 = kc * 64;
#pragma unroll
        for (int it = 0; it < 2; it++) {
            int idx = tid + it * 512;
            int row = idx >> 3, ch = idx & 7;
            int f = e0 + row;
            bool ok = f < nf;
            cpasync16(base + ST_A + toff(row, ch),
                      g_H1h + (size_t)(ok ? f : 0) * HD + k0 + ch * 8, ok ? 16 : 0);
        }
#pragma unroll
        for (int it = 0; it < 6; it++) {
            int idx = tid + it * 512;
            int row = idx >> 3, ch = idx & 7;
            int g = row >> 7, jr = row & 127;
            cpasync16(base + ST_B + toff(row, ch),
                      g_w + (size_t)(g * HD + j0g + jr) * HD + k0 + ch * 8, 16);
        }
        cpcommit();
    };

    float acc[3][2][4][4];
#pragma unroll
    for (int g = 0; g < 3; g++)
#pragma unroll
        for (int mi = 0; mi < 2; mi++)
#pragma unroll
            for (int ni = 0; ni < 4; ni++)
#pragma unroll
                for (int c = 0; c < 4; c++) acc[g][mi][ni][c] = 0.0f;

    load_chunk(0, 0);
    load_chunk(1, 1);
    cpwait<1>();
    __syncthreads();

    for (int kc = 0; kc < 8; kc++) {
        if (kc + 2 < 8) load_chunk(kc + 2, (kc + 2) % 3);

        uint32_t base = sb + SM_STAGE + (uint32_t)(kc % 3) * STAGE_BYTES;
#pragma unroll
        for (int ks = 0; ks < 4; ks++) {
            uint32_t a[2][4];
#pragma unroll
            for (int mi = 0; mi < 2; mi++) {
                int r  = esub * 32 + mi * 16 + (lane & 15);
                int ch = ks * 2 + (lane >> 4);
                ldsm4(a[mi], base + ST_A + toff(r, ch));
            }
#pragma unroll
            for (int g = 0; g < 3; g++) {
                uint32_t b[2][4];
#pragma unroll
                for (int p = 0; p < 2; p++) {
                    int r  = g * 128 + j0w + p * 16 + ((lane >> 4) << 3) + (lane & 7);
                    int ch = ks * 2 + ((lane >> 3) & 1);
                    ldsm4(b[p], base + ST_B + toff(r, ch));
                }
#pragma unroll
                for (int mi = 0; mi < 2; mi++)
#pragma unroll
                    for (int p = 0; p < 2; p++)
#pragma unroll
                        for (int q = 0; q < 2; q++)
                            mma16816(acc[g][mi][p * 2 + q], a[mi], b[p][q * 2], b[p][q * 2 + 1]);
            }
        }
        if (kc < 7) {
            if (kc + 2 < 8) cpwait<1>(); else cpwait<0>();
            __syncthreads();
        }
    }

#pragma unroll
    for (int mi = 0; mi < 2; mi++) {
#pragma unroll
        for (int rh = 0; rh < 2; rh++) {
            int f = e0 + esub * 32 + mi * 16 + rh * 8 + (lane >> 2);
            if (f >= nf) continue;
#pragma unroll
            for (int ni = 0; ni < 4; ni++) {
                int jl = j0w + ni * 8 + (lane & 3) * 2;
                int j  = j0g + jl;
#pragma unroll
                for (int g = 0; g < 3; g++) {
                    float v0 = acc[g][mi][ni][rh * 2]     + s_bias[g * 128 + jl];
                    float v1 = acc[g][mi][ni][rh * 2 + 1] + s_bias[g * 128 + jl + 1];
                    __half2 o;
                    o.x = __float2half(v0);
                    o.y = __float2half(v1);
                    *(__half2*)(g_gh2 + (size_t)f * G3 + g * HD + j) = o;
                }
            }
        }
    }
}

// ---------------------------------------------------------------------------
// Step-1 per-edge elementwise: h2[e] = GRUcell(GH2[f0] + GI[f1], H1[f0]) -> hB
// ---------------------------------------------------------------------------
__global__ void __launch_bounds__(256)
step1_edge_kernel(const int* __restrict__ mpi, int Ee) {
    int warp = (blockIdx.x * blockDim.x + threadIdx.x) >> 5;
    int lane = threadIdx.x & 31;
    if (warp >= Ee) return;
    int f0 = mpi[(size_t)warp * L];
    int f1 = mpi[(size_t)warp * L + 1];
    int j = lane * 16;

    const uint4* h1p = (const uint4*)(g_H1h + (size_t)f0 * HD + j);
    const uint4* ghr = (const uint4*)(g_gh2 + (size_t)f0 * G3 + j);
    const uint4* ghz = (const uint4*)(g_gh2 + (size_t)f0 * G3 + HD + j);
    const uint4* ghn = (const uint4*)(g_gh2 + (size_t)f0 * G3 + 2 * HD + j);
    const uint4* gir = (const uint4*)(g_GIh + (size_t)f1 * G3 + j);
    const uint4* giz = (const uint4*)(g_GIh + (size_t)f1 * G3 + HD + j);
    const uint4* gin = (const uint4*)(g_GIh + (size_t)f1 * G3 + 2 * HD + j);
    uint4* outp = (uint4*)(g_hB + (size_t)warp * HD + j);

#pragma unroll
    for (int half16 = 0; half16 < 2; half16++) {
        uint4 qh1 = h1p[half16];
        uint4 qgr = ghr[half16], qgz = ghz[half16], qgn = ghn[half16];
        uint4 qir = gir[half16], qiz = giz[half16], qin = gin[half16];
        const __half2* h1v = (const __half2*)&qh1;
        const __half2* grv = (const __half2*)&qgr;
        const __half2* gzv = (const __half2*)&qgz;
        const __half2* gnv = (const __half2*)&qgn;
        const __half2* irv = (const __half2*)&qir;
        const __half2* izv = (const __half2*)&qiz;
        const __half2* inv = (const __half2*)&qin;
        uint4 qo;
        __half2* ov = (__half2*)&qo;
#pragma unroll
        for (int k = 0; k < 4; k++) {
            float r0 = fsig(__half2float(grv[k].x) + __half2float(irv[k].x));
            float r1 = fsig(__half2float(grv[k].y) + __half2float(irv[k].y));
            float z0 = fsig(__half2float(gzv[k].x) + __half2float(izv[k].x));
            float z1 = fsig(__half2float(gzv[k].y) + __half2float(izv[k].y));
            float n0 = ftanh(__half2float(inv[k].x) + r0 * __half2float(gnv[k].x));
            float n1 = ftanh(__half2float(inv[k].y) + r1 * __half2float(gnv[k].y));
            float h0 = (1.0f - z0) * n0 + z0 * __half2float(h1v[k].x);
            float h1 = (1.0f - z1) * n1 + z1 * __half2float(h1v[k].y);
            ov[k].x = __float2half(h0);
            ov[k].y = __float2half(h1);
        }
        outp[half16] = qo;
    }
}

// ---------------------------------------------------------------------------
// GRU step, templated on MODE (R11-exact hot kernel).
// MODE 1: A = hB, O = hA  (t = 2)
// MODE 2: A = hA, O = hB  (t = 3) + fused attention logits
// ---------------------------------------------------------------------------
template<int MODE>
__global__ void __launch_bounds__(512, 1)
gru_mma_kernel(const int* __restrict__ mpi,
               const float* __restrict__ b_hh,
               const float* __restrict__ attn,
               int Ee, int t) {
    extern __shared__ char smem[];
    uint32_t sb = smem_u32(smem);
    int tid = threadIdx.x;
    int wid = tid >> 5;
    int lane = tid & 31;
    int esub = wid & 3;
    int j0w  = (wid >> 2) * 32;

    const __half* __restrict__ A = (MODE == 1) ? g_hB : g_hA;
    __half* __restrict__       O = (MODE == 1) ? g_hA : g_hB;

    int e0 = blockIdx.x * 128;
    int j0g = blockIdx.y * 128;

    float* s_bias = (float*)(smem + SM_BIAS);
    for (int i = tid; i < 384; i += 512)
        s_bias[i] = b_hh[(i >> 7) * HD + j0g + (i & 127)];
    float* s_attn = (float*)(smem + SM_ATTN);
    if (MODE == 2) {
        if (tid < 128) s_attn[tid] = attn[j0g + tid];
    }

    auto load_chunk = [&](int kc, int s) {
        uint32_t base = sb + SM_STAGE + (uint32_t)s * STAGE_BYTES;
        int k0 = kc * 64;
#pragma unroll
        for (int it = 0; it < 2; it++) {
            int idx = tid + it * 512;
            int row = idx >> 3, ch = idx & 7;
            int e = e0 + row;
            bool ok = e < Ee;
            cpasync16(base + ST_A + toff(row, ch),
                      A + (size_t)(ok ? e : 0) * HD + k0 + ch * 8, ok ? 16 : 0);
        }
#pragma unroll
        for (int it = 0; it < 6; it++) {
            int idx = tid + it * 512;
            int row = idx >> 3, ch = idx & 7;
            int g = row >> 7, jr = row & 127;
            cpasync16(base + ST_B + toff(row, ch),
                      g_w + (size_t)(g * HD + j0g + jr) * HD + k0 + ch * 8, 16);
        }
        cpcommit();
    };

    float acc[3][2][4][4];
#pragma unroll
    for (int g = 0; g < 3; g++)
#pragma unroll
        for (int mi = 0; mi < 2; mi++)
#pragma unroll
            for (int ni = 0; ni < 4; ni++)
#pragma unroll
                for (int c = 0; c < 4; c++) acc[g][mi][ni][c] = 0.0f;

    load_chunk(0, 0);
    load_chunk(1, 1);
    cpwait<1>();
    __syncthreads();

    for (int kc = 0; kc < 8; kc++) {
        if (kc + 2 < 8) load_chunk(kc + 2, (kc + 2) % 3);

        uint32_t base = sb + SM_STAGE + (uint32_t)(kc % 3) * STAGE_BYTES;
#pragma unroll
        for (int ks = 0; ks < 4; ks++) {
            uint32_t a[2][4];
#pragma unroll
            for (int mi = 0; mi < 2; mi++) {
                int r  = esub * 32 + mi * 16 + (lane & 15);
                int ch = ks * 2 + (lane >> 4);
                ldsm4(a[mi], base + ST_A + toff(r, ch));
            }
#pragma unroll
            for (int g = 0; g < 3; g++) {
                uint32_t b[2][4];
#pragma unroll
                for (int p = 0; p < 2; p++) {
                    int r  = g * 128 + j0w + p * 16 + ((lane >> 4) << 3) + (lane & 7);
                    int ch = ks * 2 + ((lane >> 3) & 1);
                    ldsm4(b[p], base + ST_B + toff(r, ch));
                }
#pragma unroll
                for (int mi = 0; mi < 2; mi++)
#pragma unroll
                    for (int p = 0; p < 2; p++)
#pragma unroll
                        for (int q = 0; q < 2; q++)
                            mma16816(acc[g][mi][p * 2 + q], a[mi], b[p][q * 2], b[p][q * 2 + 1]);
            }
        }
        if (kc < 7) {
            if (kc + 2 < 8) cpwait<1>(); else cpwait<0>();
            __syncthreads();
        }
    }

    // scratch for fused logits (stage ring dead after mainloop)
    float* s_logit = (float*)(smem + SM_STAGE);
    int hl = (wid >> 2) >> 1;
    if (MODE == 2) {
        __syncthreads();
        for (int i = tid; i < 256; i += 512) s_logit[i] = 0.0f;
        __syncthreads();
    }

#pragma unroll
    for (int mi = 0; mi < 2; mi++) {
#pragma unroll
        for (int rh = 0; rh < 2; rh++) {
            int rl = esub * 32 + mi * 16 + rh * 8 + (lane >> 2);
            int e = e0 + rl;
            float p = 0.0f;
            if (e < Ee) {
                int f = mpi[(size_t)e * L + t];
                const __half* giRow = g_GIh + (size_t)f * G3;
#pragma unroll
                for (int ni = 0; ni < 4; ni++) {
                    int jl = j0w + ni * 8 + (lane & 3) * 2;
                    int j  = j0g + jl;
                    float gr0 = acc[0][mi][ni][rh * 2], gr1 = acc[0][mi][ni][rh * 2 + 1];
                    float gz0 = acc[1][mi][ni][rh * 2], gz1 = acc[1][mi][ni][rh * 2 + 1];
                    float gn0 = acc[2][mi][ni][rh * 2], gn1 = acc[2][mi][ni][rh * 2 + 1];
                    __half2 ir = *(const __half2*)(giRow + j);
                    __half2 iz = *(const __half2*)(giRow + HD + j);
                    __half2 in = *(const __half2*)(giRow + 2 * HD + j);
                    float r0 = fsig(gr0 + s_bias[jl]           + __half2float(ir.x));
                    float r1 = fsig(gr1 + s_bias[jl + 1]       + __half2float(ir.y));
                    float z0 = fsig(gz0 + s_bias[128 + jl]     + __half2float(iz.x));
                    float z1 = fsig(gz1 + s_bias[128 + jl + 1] + __half2float(iz.y));
                    float n0 = ftanh(__half2float(in.x) + r0 * (gn0 + s_bias[256 + jl]));
                    float n1 = ftanh(__half2float(in.y) + r1 * (gn1 + s_bias[256 + jl + 1]));
                    __half2 hp = *(const __half2*)(A + (size_t)e * HD + j);
                    float h0 = (1.0f - z0) * n0 + z0 * __half2float(hp.x);
                    float h1 = (1.0f - z1) * n1 + z1 * __half2float(hp.y);
                    __half2 oh;
                    oh.x = __float2half(h0);
                    oh.y = __float2half(h1);
                    *(__half2*)(O + (size_t)e * HD + j) = oh;
                    if (MODE == 2) {
                        p += h0 * s_attn[jl] + h1 * s_attn[jl + 1];
                    }
                }
            }
            if (MODE == 2) {
                p += __shfl_xor_sync(0xffffffff, p, 1);
                p += __shfl_xor_sync(0xffffffff, p, 2);
                if ((lane & 3) == 0 && e < Ee)
                    atomicAdd(&s_logit[rl * 2 + hl], p);
            }
        }
    }

    if (MODE == 2) {
        __syncthreads();
        if (tid < 256) {
            int rl = tid >> 1, h2 = tid & 1;
            int e = e0 + rl;
            if (e < Ee) {
                float v = s_logit[tid];
                g_a[(size_t)e * H + (j0g >> 6) + h2] = v > 0.0f ? v : 0.001f * v;
            }
        }
    }
}

// ---------------------------------------------------------------------------
// CSR build
// ---------------------------------------------------------------------------
__global__ void count_kernel(const int* __restrict__ dst, int Ee) {
    int i = blockIdx.x * blockDim.x + threadIdx.x;
    if (i < Ee) atomicAdd(&g_deg[dst[i]], 1);
}
__global__ void scan_kernel(int nn, int Ee) {
    __shared__ int ssum[1024];
    int t = threadIdx.x;
    int chunk = (nn + 1023) >> 10;
    int lo = t * chunk, hi = lo + chunk;
    if (hi > nn) hi = nn;
    int s = 0;
    for (int i = lo; i < hi; i++) s += g_deg[i];
    ssum[t] = s;
    __syncthreads();
    for (int off = 1; off < 1024; off <<= 1) {
        int v = (t >= off) ? ssum[t - off] : 0;
        __syncthreads();
        ssum[t] += v;
        __syncthreads();
    }
    int run = (t == 0) ? 0 : ssum[t - 1];
    for (int i = lo; i < hi; i++) {
        g_rowptr[i] = run;
        g_cursor[i] = run;
        run += g_deg[i];
    }
    if (t == 0) g_rowptr[nn] = Ee;
}
__global__ void fill_kernel(const int* __restrict__ dst, int Ee) {
    int i = blockIdx.x * blockDim.x + threadIdx.x;
    if (i < Ee) {
        int p = atomicAdd(&g_cursor[dst[i]], 1);
        g_eidx[p] = i;
    }
}

// ---------------------------------------------------------------------------
// Per-node segment softmax + weighted scatter: one warp per node, no atomics.
// ---------------------------------------------------------------------------
__global__ void node_attn_kernel(float* __restrict__ out, int nn) {
    int warp = (blockIdx.x * blockDim.x + threadIdx.x) >> 5;
    int lane = threadIdx.x & 31;
    if (warp >= nn) return;
    int start = g_rowptr[warp];
    int end   = g_rowptr[warp + 1];

    int sub = lane >> 3;
    int hh  = lane & 7;
    float m = -3.0e38f;
    for (int i = start + sub; i < end; i += 4)
        m = fmaxf(m, g_a[(size_t)g_eidx[i] * H + hh]);
    m = fmaxf(m, __shfl_xor_sync(0xffffffff, m, 8));
    m = fmaxf(m, __shfl_xor_sync(0xffffffff, m, 16));
    float s = 0.0f;
    for (int i = start + sub; i < end; i += 4)
        s += __expf(g_a[(size_t)g_eidx[i] * H + hh] - m);
    s += __shfl_xor_sync(0xffffffff, s, 8);
    s += __shfl_xor_sync(0xffffffff, s, 16);

    int h = lane >> 2;
    float mh  = __shfl_sync(0xffffffff, m, h);
    float inv = __fdividef(1.0f, fmaxf(__shfl_sync(0xffffffff, s, h), 1e-12f));

    float acc[16];
#pragma unroll
    for (int k = 0; k < 16; k++) acc[k] = 0.0f;

    for (int i = start; i < end; i++) {
        int e = g_eidx[i];
        float w = __expf(g_a[(size_t)e * H + h] - mh) * inv;
        const uint4* p = (const uint4*)(g_hB + (size_t)e * HD + lane * 16);
        uint4 q0 = p[0], q1 = p[1];
        const __half2* c0 = (const __half2*)&q0;
        const __half2* c1 = (const __half2*)&q1;
#pragma unroll
        for (int k = 0; k < 4; k++) {
            acc[2 * k]     += w * __half2float(c0[k].x);
            acc[2 * k + 1] += w * __half2float(c0[k].y);
            acc[8 + 2 * k]     += w * __half2float(c1[k].x);
            acc[8 + 2 * k + 1] += w * __half2float(c1[k].y);
        }
    }
    float4* o = (float4*)(out + (size_t)warp * HD + lane * 16);
#pragma unroll
    for (int k = 0; k < 4; k++)
        o[k] = make_float4(acc[4 * k], acc[4 * k + 1], acc[4 * k + 2], acc[4 * k + 3]);
}

// ---------------------------------------------------------------------------
extern "C" void kernel_launch(void* const* d_in, const int* in_sizes, int n_in,
                              void* d_out, int out_size) {
    int off = (n_in >= 9) ? 1 : 0;
    const float* feat = (const float*)d_in[0];
    const int*   mpi  = (const int*)d_in[1];
    const int*   dst  = (const int*)d_in[2];
    const float* w_ih = (const float*)d_in[3 + off];
    const float* w_hh = (const float*)d_in[4 + off];
    const float* b_ih = (const float*)d_in[5 + off];
    const float* b_hh = (const float*)d_in[6 + off];
    const float* attn = (const float*)d_in[7 + off];
    float* out = (float*)d_out;

    int E  = in_sizes[2];
    int nf = in_sizes[0] / D;
    int nn = out_size / HD;

    cudaFuncSetAttribute(gru_mma_kernel<1>, cudaFuncAttributeMaxDynamicSharedMemorySize, SMEM_TOTAL);
    cudaFuncSetAttribute(gru_mma_kernel<2>, cudaFuncAttributeMaxDynamicSharedMemorySize, SMEM_TOTAL);
    cudaFuncSetAttribute(gh2_mma_kernel, cudaFuncAttributeMaxDynamicSharedMemorySize, SMEM_TOTAL);
    cudaFuncSetAttribute(gi3_mma_kernel, cudaFuncAttributeMaxDynamicSharedMemorySize, GI3_TOTAL);

    init_kernel<<<(nn + 255) / 256, 256>>>(nn);

    feat2h_kernel<<<(nf * D + 255) / 256, 256>>>(feat, nf * D);
    convert_w_kernel<<<(G3 * HD + 255) / 256, 256>>>(w_hh);
    convert_wih_kernel<<<(G3 * D + 255) / 256, 256>>>(w_ih);

    // GI + fused H1
    dim3 gi3_grid((nf + 127) / 128, HD / 128);
    gi3_mma_kernel<<<gi3_grid, 512, GI3_TOTAL>>>(b_ih, b_hh, nf);

    // CSR build
    count_kernel<<<(E + 255) / 256, 256>>>(dst, E);
    scan_kernel<<<1, 1024>>>(nn, E);
    fill_kernel<<<(E + 255) / 256, 256>>>(dst, E);

    // Step 1 dedup: per-feature GEMM + per-edge elementwise cell
    dim3 gh2_grid((nf + 127) / 128, HD / 128);
    gh2_mma_kernel<<<gh2_grid, 512, SMEM_TOTAL>>>(b_hh, nf);
    step1_edge_kernel<<<(E * 32 + 255) / 256, 256>>>(mpi, E);   // -> hB

    // Steps 2,3 (step 3 fuses attention logits into its epilogue)
    dim3 gru_grid((E + 127) / 128, HD / 128);
    gru_mma_kernel<1><<<gru_grid, 512, SMEM_TOTAL>>>(mpi, b_hh, attn, E, 2);  // hB -> hA
    gru_mma_kernel<2><<<gru_grid, 512, SMEM_TOTAL>>>(mpi, b_hh, attn, E, 3);  // hA -> hB (+logits)

    node_attn_kernel<<<(nn * 32 + 255) / 256, 256>>>(out, nn);
}